// round 14
// baseline (speedup 1.0000x reference)
#include <cuda_runtime.h>
#include <cuda_fp16.h>
#include <cstdint>

#define BATCH 2
#define SEQ 2048
#define DMODEL 1024
#define NH 16
#define HD 64
#define MROWS (BATCH * SEQ)   // 4096

// Scratch (allocation-free rule: __device__ globals)
__device__ __half g_Xh[MROWS * DMODEL];          // x in fp16
__device__ __half g_Qh[MROWS * DMODEL];          // (B,H,S,hd), pre-scaled 1/8
__device__ __half g_Kh[MROWS * DMODEL];
__device__ __half g_Vh[MROWS * DMODEL];
__device__ __half g_Ch[MROWS * DMODEL];          // ctx (B,S,D) fp16
__device__ __half g_Wth[4 * DMODEL * DMODEL];    // weights [N][K] fp16
__device__ float  g_mbias[BATCH * SEQ];          // 0 or -1e30 per key
__device__ int    g_tflag[BATCH * 32];           // per 64-key tile: has pad?

// ---------------------------------------------------------------------------
// helpers
// ---------------------------------------------------------------------------
__device__ __forceinline__ void mma_f16(float* c, const unsigned* a,
                                        unsigned b0, unsigned b1) {
    asm volatile(
        "mma.sync.aligned.m16n8k16.row.col.f32.f16.f16.f32 "
        "{%0,%1,%2,%3}, {%4,%5,%6,%7}, {%8,%9}, {%0,%1,%2,%3};"
        : "+f"(c[0]), "+f"(c[1]), "+f"(c[2]), "+f"(c[3])
        : "r"(a[0]), "r"(a[1]), "r"(a[2]), "r"(a[3]), "r"(b0), "r"(b1));
}

__device__ __forceinline__ uint32_t smem_u32(const void* p) {
    return (uint32_t)__cvta_generic_to_shared(p);
}
__device__ __forceinline__ void ldsm4(unsigned* r, uint32_t a) {
    asm volatile("ldmatrix.sync.aligned.m8n8.x4.shared.b16 {%0,%1,%2,%3}, [%4];"
                 : "=r"(r[0]), "=r"(r[1]), "=r"(r[2]), "=r"(r[3]) : "r"(a));
}
__device__ __forceinline__ void ldsm4t(unsigned* r, uint32_t a) {
    asm volatile("ldmatrix.sync.aligned.m8n8.x4.trans.shared.b16 {%0,%1,%2,%3}, [%4];"
                 : "=r"(r[0]), "=r"(r[1]), "=r"(r[2]), "=r"(r[3]) : "r"(a));
}
__device__ __forceinline__ unsigned h2u(__half2 h) {
    return *reinterpret_cast<unsigned*>(&h);
}

__device__ __forceinline__ void cpa16(void* s, const void* g) {
    unsigned a = (unsigned)__cvta_generic_to_shared(s);
    asm volatile("cp.async.cg.shared.global [%0], [%1], 16;" :: "r"(a), "l"(g));
}
__device__ __forceinline__ void cp_commit() {
    asm volatile("cp.async.commit_group;");
}
template <int N>
__device__ __forceinline__ void cp_wait() {
    asm volatile("cp.async.wait_group %0;" :: "n"(N));
}

// ---------------------------------------------------------------------------
// merged prep kernel (one launch):
//   bid [0, 4096)      : x -> fp16 (1M float4)
//   bid [4096, 8192)   : W[K][N] fp32 -> g_Wth[N][K] fp16 (transposed)
//   bid [8192, 8209)   : mask -> bias + per-tile pad flags
// ---------------------------------------------------------------------------
__global__ __launch_bounds__(256) void prep_all(
    const float4* __restrict__ x,
    const float* __restrict__ wq, const float* __restrict__ wk,
    const float* __restrict__ wv, const float* __restrict__ wo,
    const int* __restrict__ mask)
{
    const int bid = blockIdx.x;
    const int tid = threadIdx.x;

    if (bid < 4096) {
        const int i = bid * 256 + tid;
        float4 v = x[i];
        __half2* dst = reinterpret_cast<__half2*>(g_Xh);
        dst[2 * i]     = __floats2half2_rn(v.x, v.y);
        dst[2 * i + 1] = __floats2half2_rn(v.z, v.w);
    } else if (bid < 8192) {
        __shared__ float tile[32][33];
        const int widx = bid - 4096;
        const int z = widx >> 10;
        const int nb = (widx & 31) * 32;
        const int kb = ((widx >> 5) & 31) * 32;
        const float* W = (z == 0) ? wq : (z == 1) ? wk : (z == 2) ? wv : wo;
        __half* Wt = g_Wth + (size_t)z * DMODEL * DMODEL;
        const int tx = tid & 31;
        const int ty = tid >> 5;          // 0..7
#pragma unroll
        for (int j = 0; j < 4; j++) {
            const int r = ty + j * 8;     // k within tile
            tile[r][tx] = W[(size_t)(kb + r) * DMODEL + nb + tx];
        }
        __syncthreads();
#pragma unroll
        for (int j = 0; j < 4; j++) {
            const int r = ty + j * 8;     // n within tile
            Wt[(size_t)(nb + r) * DMODEL + kb + tx] =
                __float2half_rn(tile[tx][r]);
        }
    } else {
        const int gid = (bid - 8192) * 256 + tid;
        if (gid < BATCH * SEQ) {
            g_mbias[gid] = (mask[gid] != 0) ? 0.0f : -1e30f;
        } else if (gid - BATCH * SEQ < BATCH * 32) {
            const int t = gid - BATCH * SEQ;
            const int* mp = mask + (t >> 5) * SEQ + (t & 31) * 64;
            int anypad = 0;
#pragma unroll 8
            for (int i = 0; i < 64; i++) anypad |= (mp[i] == 0);
            g_tflag[t] = anypad;
        }
    }
}

// ---------------------------------------------------------------------------
// fp16 tensor-core GEMM (m16n8k16 + ldmatrix), BK=64, 3-stage cp.async
// pipeline with wrapped stage pointers, ONE barrier per 64-MMA iteration,
// warp-skewed k-order.
// C[M,N] = A[M,K] @ W^T (W stored [N][K]) + bias
// BM=128 BN=128 BK=64, 256 thr (8 warps 2m x 4n), warp tile 64x32, 2 CTA/SM.
// MODE 0: fused QKV (z=blockIdx.z), head-split fp16 out (z==0 pre-scaled 1/8).
// MODE 1: Wo, fp32 row-major out.
// Stage: A 128x72h + B 128x72h = 36864 B. 3 stages = 110592 B.
// ---------------------------------------------------------------------------
#define APH 72
#define BOFF 9216               // halves: A stage size (128*72)
#define STGH 18432              // halves per stage
#define GEMM_SMEM (3 * STGH * 2)   // 110592 B

template <int MODE>
__global__ __launch_bounds__(256, 2) void gemm_h(
    const float* __restrict__ b0p, const float* __restrict__ b1p,
    const float* __restrict__ b2p, float* __restrict__ outp)
{
    extern __shared__ __half sh[];

    const int z = (MODE == 0) ? blockIdx.z : 3;
    const __half* __restrict__ A = (MODE == 0) ? g_Xh : g_Ch;
    const __half* __restrict__ W = g_Wth + (size_t)z * DMODEL * DMODEL;
    const float* bias = (MODE == 0)
        ? ((z == 0) ? b0p : (z == 1) ? b1p : b2p) : b0p;
    __half* dstQ = (z == 0) ? g_Qh : (z == 1) ? g_Kh : g_Vh;

    const int tid = threadIdx.x;
    const int lane = tid & 31;
    const int warp = tid >> 5;
    const int g = lane >> 2;
    const int tg = lane & 3;
    const int m0 = blockIdx.y * 128;
    const int n0 = blockIdx.x * 128;
    const int wm = (warp >> 2) * 64;
    const int wn = (warp & 3) * 32;
    const int wskew = warp & 1;         // k-step order skew

    float acc[4][4][4];
#pragma unroll
    for (int mi = 0; mi < 4; mi++)
#pragma unroll
        for (int ni = 0; ni < 4; ni++)
#pragma unroll
            for (int q = 0; q < 4; q++) acc[mi][ni][q] = 0.0f;

    // fill addressing: thread covers rows fr+32u (u=0..3), 8 halves at col fk,
    // for both A and B tiles. 8 cp.async x 16B per thread per fill.
    const int fr = tid >> 3;            // 0..31
    const int fk = (tid & 7) * 8;       // 0..56
    const __half* aS = A + (size_t)(m0 + fr) * DMODEL + fk;
    const __half* bS = W + (size_t)(n0 + fr) * DMODEL + fk;
    const int dA = fr * APH + fk;
    const int dB = BOFF + fr * APH + fk;

    auto fill = [&](int t, __half* s) {
        const int k0 = t * 64;
#pragma unroll
        for (int u = 0; u < 4; u++) {
            cpa16(s + dA + u * 32 * APH, aS + k0 + (size_t)u * 32 * DMODEL);
            cpa16(s + dB + u * 32 * APH, bS + k0 + (size_t)u * 32 * DMODEL);
        }
    };

    const int lrow = lane & 15;
    const int lcol = (lane >> 4) * 8;

    auto compute = [&](const __half* As) {
        const __half* Bs = As + BOFF;
#pragma unroll
        for (int ks = 0; ks < 4; ks++) {
            const int kb = (ks ^ wskew) * 16;   // warp-skewed order
            unsigned a[4][4], b[4][2];
#pragma unroll
            for (int mi = 0; mi < 4; mi++)
                ldsm4(a[mi],
                      smem_u32(As + (wm + mi * 16 + lrow) * APH + kb + lcol));
            {
                unsigned t0[4], t1[4];
                ldsm4(t0, smem_u32(Bs + (wn + lrow) * APH + kb + lcol));
                ldsm4(t1, smem_u32(Bs + (wn + 16 + lrow) * APH + kb + lcol));
                b[0][0] = t0[0]; b[1][0] = t0[1]; b[0][1] = t0[2]; b[1][1] = t0[3];
                b[2][0] = t1[0]; b[3][0] = t1[1]; b[2][1] = t1[2]; b[3][1] = t1[3];
            }
#pragma unroll
            for (int mi = 0; mi < 4; mi++)
#pragma unroll
                for (int ni = 0; ni < 4; ni++)
                    mma_f16(acc[mi][ni], a[mi], b[ni][0], b[ni][1]);
        }
    };

    // prologue: stages 0 and 1
    fill(0, sh);           cp_commit();
    fill(1, sh + STGH);    cp_commit();

    // wrapped stage pointers
    __half* stC = sh;                    // compute stage for t
    __half* stF = sh + 2 * STGH;         // fill stage for t+2
    __half* const send = sh + 3 * STGH;

#pragma unroll 1
    for (int t = 0; t < 16; t++) {
        cp_wait<1>();          // stage t complete
        __syncthreads();       // all warps done with stage (t-1)%3
        if (t + 2 < 16) fill(t + 2, stF);
        cp_commit();           // always commit
        compute(stC);
        stC += STGH; if (stC == send) stC = sh;
        stF += STGH; if (stF == send) stF = sh;
    }

    // epilogue
    const float qsc = (MODE == 0 && z == 0) ? 0.125f : 1.0f;
#pragma unroll
    for (int mi = 0; mi < 4; mi++) {
#pragma unroll
        for (int ni = 0; ni < 4; ni++) {
            const int row0 = m0 + wm + mi * 16 + g;
            const int row1 = row0 + 8;
            const int col = n0 + wn + ni * 8 + 2 * tg;
            const float bb0 = bias[col];
            const float bb1 = bias[col + 1];
            if (MODE == 1) {
                float2 v0 = make_float2(acc[mi][ni][0] + bb0,
                                        acc[mi][ni][1] + bb1);
                float2 v1 = make_float2(acc[mi][ni][2] + bb0,
                                        acc[mi][ni][3] + bb1);
                *reinterpret_cast<float2*>(&outp[(size_t)row0 * DMODEL + col]) = v0;
                *reinterpret_cast<float2*>(&outp[(size_t)row1 * DMODEL + col]) = v1;
            } else {
                __half2 h0 = __floats2half2_rn((acc[mi][ni][0] + bb0) * qsc,
                                               (acc[mi][ni][1] + bb1) * qsc);
                __half2 h1 = __floats2half2_rn((acc[mi][ni][2] + bb0) * qsc,
                                               (acc[mi][ni][3] + bb1) * qsc);
                const int h = col >> 6;
                const int d = col & (HD - 1);
                {
                    const int b = row0 >> 11, s = row0 & (SEQ - 1);
                    *reinterpret_cast<__half2*>(
                        &dstQ[((size_t)(b * NH + h) * SEQ + s) * HD + d]) = h0;
                }
                {
                    const int b = row1 >> 11, s = row1 & (SEQ - 1);
                    *reinterpret_cast<__half2*>(
                        &dstQ[((size_t)(b * NH + h) * SEQ + s) * HD + d]) = h1;
                }
            }
        }
    }
}

// ---------------------------------------------------------------------------
// fp16 flash attention (m16n8k16) — R13 version (best measured).
// 128 threads (4 warps), 64 q/block, 64-key tiles, 3-stage cp.async pipeline
// with wrapped stage pointers, ONE __syncthreads per tile. P in registers.
// Q pre-scaled by 1/8. Heavy-first block order. 3 CTAs/SM.
// grid = (SEQ/64, BATCH*NH)
// ---------------------------------------------------------------------------
#define QPH 72
#define KVSH (2 * 64 * QPH)                        // halves per KV stage
#define FA_SMEM ((64 * QPH + 3 * KVSH) * 2)        // Q + 3 stages -> 64512 B

__global__ __launch_bounds__(128) void flash_h()
{
    extern __shared__ __half fsm[];
    __half* Qs = fsm;

    const int tid = threadIdx.x;
    const int lane = tid & 31;
    const int warp = tid >> 5;
    const int g = lane >> 2;
    const int tg = lane & 3;
    const int wm = warp * 16;
    const int lrow = lane & 15;
    const int lcol = (lane >> 4) * 8;

    const int bh = blockIdx.y;
    const int b = bh >> 4;
    const int h = bh & 15;
    const int qt = gridDim.x - 1 - blockIdx.x;   // heavy-first
    const int q0 = qt * 64;
    const size_t base = (size_t)bh * SEQ * HD;

    auto fillkv = [&](int kt, __half* Kd) {
        __half* Vd = Kd + 64 * QPH;
        const int k0 = kt * 64;
#pragma unroll
        for (int u = 0; u < 8; u++) {
            const int c = tid + 128 * u;          // 0..1023
            if (u < 4) {
                const int r = c >> 3, cc = (c & 7) * 8;
                cpa16(Kd + r * QPH + cc, g_Kh + base + (size_t)(k0 + r) * HD + cc);
            } else {
                const int c2 = c - 512;
                const int r = c2 >> 3, cc = (c2 & 7) * 8;
                cpa16(Vd + r * QPH + cc, g_Vh + base + (size_t)(k0 + r) * HD + cc);
            }
        }
    };

    __half* const kvbase = fsm + 64 * QPH;
    __half* const kvend  = kvbase + 3 * KVSH;

#pragma unroll
    for (int u = 0; u < 4; u++) {
        const int c = tid + 128 * u;              // 0..511
        const int r = c >> 3, cc = (c & 7) * 8;
        cpa16(Qs + r * QPH + cc, g_Qh + base + (size_t)(q0 + r) * HD + cc);
    }
    fillkv(0, kvbase);
    cp_commit();
    if (qt >= 1) fillkv(1, kvbase + KVSH);
    cp_commit();

    cp_wait<1>();
    __syncthreads();

    unsigned qf[4][4];
#pragma unroll
    for (int j = 0; j < 4; j++)
        ldsm4(qf[j], smem_u32(Qs + (wm + lrow) * QPH + j * 16 + lcol));

    float o[8][4];
#pragma unroll
    for (int nt = 0; nt < 8; nt++)
#pragma unroll
        for (int q = 0; q < 4; q++) o[nt][q] = 0.0f;
    float m0r = -1e30f, m1r = -1e30f, l0 = 0.0f, l1 = 0.0f;

    const int qr0 = q0 + wm + g;
    const int qr1 = qr0 + 8;
    const float* mb = g_mbias + b * SEQ;
    const int* tfl = g_tflag + (b << 5);

    __half* KsP = kvbase;
    __half* KfP = kvbase + 2 * KVSH;

#pragma unroll 1
    for (int kt = 0; kt <= qt; kt++) {
        const int k0 = kt * 64;
        cp_wait<1>();
        __syncthreads();
        if (kt + 2 <= qt) fillkv(kt + 2, KfP);
        cp_commit();

        const int need_pad = tfl[kt];
        const __half* Ks = KsP;
        const __half* Vs = KsP + 64 * QPH;
        const bool diag = (kt == qt);

        float S[8][4];
#pragma unroll
        for (int nt = 0; nt < 8; nt++)
#pragma unroll
            for (int q = 0; q < 4; q++) S[nt][q] = 0.0f;
#pragma unroll
        for (int j = 0; j < 4; j++) {
            const int kb = j * 16;
            unsigned bf[8][2];
#pragma unroll
            for (int p = 0; p < 4; p++) {
                unsigned tt[4];
                ldsm4(tt, smem_u32(Ks + (p * 16 + lrow) * QPH + kb + lcol));
                bf[2 * p][0] = tt[0]; bf[2 * p + 1][0] = tt[1];
                bf[2 * p][1] = tt[2]; bf[2 * p + 1][1] = tt[3];
            }
#pragma unroll
            for (int nt = 0; nt < 8; nt++)
                mma_f16(S[nt], qf[j], bf[nt][0], bf[nt][1]);
        }

        if (diag) {
#pragma unroll
            for (int nt = 0; nt < 8; nt++) {
                const int kk0 = k0 + nt * 8 + 2 * tg;
#pragma unroll
                for (int j = 0; j < 2; j++) {
                    const int kk = kk0 + j;
                    if (kk > qr0) S[nt][j] = -1e30f;
                    if (kk > qr1) S[nt][2 + j] = -1e30f;
                }
            }
        }
        if (need_pad) {
#pragma unroll
            for (int nt = 0; nt < 8; nt++) {
                const float2 bb = *reinterpret_cast<const float2*>(
                    mb + k0 + nt * 8 + 2 * tg);
                S[nt][0] += bb.x; S[nt][1] += bb.y;
                S[nt][2] += bb.x; S[nt][3] += bb.y;
            }
        }

        float mt0 = -1e30f, mt1 = -1e30f;
#pragma unroll
        for (int nt = 0; nt < 8; nt++) {
            mt0 = fmaxf(mt0, fmaxf(S[nt][0], S[nt][1]));
            mt1 = fmaxf(mt1, fmaxf(S[nt][2], S[nt][3]));
        }
        mt0 = fmaxf(mt0, __shfl_xor_sync(0xffffffffu, mt0, 1));
        mt0 = fmaxf(mt0, __shfl_xor_sync(0xffffffffu, mt0, 2));
        mt1 = fmaxf(mt1, __shfl_xor_sync(0xffffffffu, mt1, 1));
        mt1 = fmaxf(mt1, __shfl_xor_sync(0xffffffffu, mt1, 2));
        const float mn0 = fmaxf(m0r, mt0);
        const float mn1 = fmaxf(m1r, mt1);
        const float a0 = __expf(m0r - mn0);
        const float a1 = __expf(m1r - mn1);

        unsigned pa[4][4];
        float s0 = 0.0f, s1 = 0.0f;
#pragma unroll
        for (int nt = 0; nt < 8; nt++) {
            const float p00 = __expf(S[nt][0] - mn0);
            const float p01 = __expf(S[nt][1] - mn0);
            const float p10 = __expf(S[nt][2] - mn1);
            const float p11 = __expf(S[nt][3] - mn1);
            s0 += p00 + p01;
            s1 += p10 + p11;
            const int j = nt >> 1;
            const int hh = (nt & 1) * 2;
            pa[j][hh]     = h2u(__floats2half2_rn(p00, p01));
            pa[j][hh + 1] = h2u(__floats2half2_rn(p10, p11));
        }
        s0 += __shfl_xor_sync(0xffffffffu, s0, 1);
        s0 += __shfl_xor_sync(0xffffffffu, s0, 2);
        s1 += __shfl_xor_sync(0xffffffffu, s1, 1);
        s1 += __shfl_xor_sync(0xffffffffu, s1, 2);
        l0 = l0 * a0 + s0;
        l1 = l1 * a1 + s1;
        m0r = mn0;
        m1r = mn1;
#pragma unroll
        for (int nt = 0; nt < 8; nt++) {
            o[nt][0] *= a0; o[nt][1] *= a0;
            o[nt][2] *= a1; o[nt][3] *= a1;
        }

#pragma unroll
        for (int j = 0; j < 4; j++) {
            const int kb = j * 16;
            unsigned bv[8][2];
#pragma unroll
            for (int p = 0; p < 4; p++) {
                unsigned tt[4];
                ldsm4t(tt, smem_u32(
                    Vs + (kb + (lane >> 4) * 8 + (lane & 7)) * QPH
                       + 8 * (2 * p + ((lane >> 3) & 1))));
                bv[2 * p][0] = tt[0]; bv[2 * p + 1][0] = tt[1];
                bv[2 * p][1] = tt[2]; bv[2 * p + 1][1] = tt[3];
            }
#pragma unroll
            for (int nt = 0; nt < 8; nt++)
                mma_f16(o[nt], pa[j], bv[nt][0], bv[nt][1]);
        }

        KsP += KVSH; if (KsP == kvend) KsP = kvbase;
        KfP += KVSH; if (KfP == kvend) KfP = kvbase;
    }

    const float i0 = 1.0f / l0;
    const float i1 = 1.0f / l1;
#pragma unroll
    for (int nt = 0; nt < 8; nt++) {
        const int d = nt * 8 + 2 * tg;
        __half* p0 = &g_Ch[((size_t)(b * SEQ + qr0)) * DMODEL + h * HD + d];
        __half* p1 = &g_Ch[((size_t)(b * SEQ + qr1)) * DMODEL + h * HD + d];
        *reinterpret_cast<__half2*>(p0) =
            __floats2half2_rn(o[nt][0] * i0, o[nt][1] * i0);
        *reinterpret_cast<__half2*>(p1) =
            __floats2half2_rn(o[nt][2] * i1, o[nt][3] * i1);
    }
}

// ---------------------------------------------------------------------------
extern "C" void kernel_launch(void* const* d_in, const int* in_sizes, int n_in,
                              void* d_out, int out_size)
{
    const float* x     = (const float*)d_in[0];
    const int*   amask = (const int*)  d_in[1];
    const float* Wq    = (const float*)d_in[2];
    const float* bq    = (const float*)d_in[3];
    const float* Wk    = (const float*)d_in[4];
    const float* bk    = (const float*)d_in[5];
    const float* Wv    = (const float*)d_in[6];
    const float* bv    = (const float*)d_in[7];
    const float* Wo    = (const float*)d_in[8];
    const float* bo    = (const float*)d_in[9];
    float* out = (float*)d_out;

    // 1. merged prep: x -> fp16, weights -> transposed fp16, mask -> bias
    prep_all<<<8209, 256>>>((const float4*)x, Wq, Wk, Wv, Wo, amask);

    cudaFuncSetAttribute(gemm_h<0>,
                         cudaFuncAttributeMaxDynamicSharedMemorySize, GEMM_SMEM);
    cudaFuncSetAttribute(gemm_h<1>,
                         cudaFuncAttributeMaxDynamicSharedMemorySize, GEMM_SMEM);

    // 2. fused QKV projection (BK=64, 3-stage)
    gemm_h<0><<<dim3(DMODEL / 128, MROWS / 128, 3), 256, GEMM_SMEM>>>(
        bq, bk, bv, nullptr);

    // 3. flash attention
    cudaFuncSetAttribute(flash_h,
                         cudaFuncAttributeMaxDynamicSharedMemorySize, FA_SMEM);
    flash_h<<<dim3(SEQ / 64, BATCH * NH), 128, FA_SMEM>>>();

    // 4. output projection
    gemm_h<1><<<dim3(DMODEL / 128, MROWS / 128, 1), 256, GEMM_SMEM>>>(
        bo, nullptr, nullptr, out);
}

// round 15
// speedup vs baseline: 1.0028x; 1.0028x over previous
#include <cuda_runtime.h>
#include <cuda_fp16.h>
#include <cstdint>

#define BATCH 2
#define SEQ 2048
#define DMODEL 1024
#define NH 16
#define HD 64
#define MROWS (BATCH * SEQ)   // 4096

// Scratch (allocation-free rule: __device__ globals)
__device__ __half g_Xh[MROWS * DMODEL];          // x in fp16
__device__ __half g_Qh[MROWS * DMODEL];          // (B,H,S,hd), scaled log2e/8
__device__ __half g_Kh[MROWS * DMODEL];
__device__ __half g_Vh[MROWS * DMODEL];
__device__ __half g_Ch[MROWS * DMODEL];          // ctx (B,S,D) fp16
__device__ __half g_Wth[4 * DMODEL * DMODEL];    // weights [N][K] fp16
__device__ float  g_mbias[BATCH * SEQ];          // 0 or -1e30 per key
__device__ int    g_tflag[BATCH * 32];           // per 64-key tile: has pad?

// ---------------------------------------------------------------------------
// helpers
// ---------------------------------------------------------------------------
__device__ __forceinline__ void mma_f16(float* c, const unsigned* a,
                                        unsigned b0, unsigned b1) {
    asm volatile(
        "mma.sync.aligned.m16n8k16.row.col.f32.f16.f16.f32 "
        "{%0,%1,%2,%3}, {%4,%5,%6,%7}, {%8,%9}, {%0,%1,%2,%3};"
        : "+f"(c[0]), "+f"(c[1]), "+f"(c[2]), "+f"(c[3])
        : "r"(a[0]), "r"(a[1]), "r"(a[2]), "r"(a[3]), "r"(b0), "r"(b1));
}

__device__ __forceinline__ uint32_t smem_u32(const void* p) {
    return (uint32_t)__cvta_generic_to_shared(p);
}
__device__ __forceinline__ void ldsm4(unsigned* r, uint32_t a) {
    asm volatile("ldmatrix.sync.aligned.m8n8.x4.shared.b16 {%0,%1,%2,%3}, [%4];"
                 : "=r"(r[0]), "=r"(r[1]), "=r"(r[2]), "=r"(r[3]) : "r"(a));
}
__device__ __forceinline__ void ldsm4t(unsigned* r, uint32_t a) {
    asm volatile("ldmatrix.sync.aligned.m8n8.x4.trans.shared.b16 {%0,%1,%2,%3}, [%4];"
                 : "=r"(r[0]), "=r"(r[1]), "=r"(r[2]), "=r"(r[3]) : "r"(a));
}
__device__ __forceinline__ unsigned h2u(__half2 h) {
    return *reinterpret_cast<unsigned*>(&h);
}
__device__ __forceinline__ float ex2f(float x) {   // raw 2^x, single MUFU op
    float r;
    asm("ex2.approx.f32 %0, %1;" : "=f"(r) : "f"(x));
    return r;
}

__device__ __forceinline__ void cpa16(void* s, const void* g) {
    unsigned a = (unsigned)__cvta_generic_to_shared(s);
    asm volatile("cp.async.cg.shared.global [%0], [%1], 16;" :: "r"(a), "l"(g));
}
__device__ __forceinline__ void cp_commit() {
    asm volatile("cp.async.commit_group;");
}
template <int N>
__device__ __forceinline__ void cp_wait() {
    asm volatile("cp.async.wait_group %0;" :: "n"(N));
}

// ---------------------------------------------------------------------------
// merged prep kernel (one launch):
//   bid [0, 4096)      : x -> fp16 (1M float4)
//   bid [4096, 8192)   : W[K][N] fp32 -> g_Wth[N][K] fp16 (transposed)
//   bid [8192, 8209)   : mask -> bias + per-tile pad flags
// ---------------------------------------------------------------------------
__global__ __launch_bounds__(256) void prep_all(
    const float4* __restrict__ x,
    const float* __restrict__ wq, const float* __restrict__ wk,
    const float* __restrict__ wv, const float* __restrict__ wo,
    const int* __restrict__ mask)
{
    const int bid = blockIdx.x;
    const int tid = threadIdx.x;

    if (bid < 4096) {
        const int i = bid * 256 + tid;
        float4 v = x[i];
        __half2* dst = reinterpret_cast<__half2*>(g_Xh);
        dst[2 * i]     = __floats2half2_rn(v.x, v.y);
        dst[2 * i + 1] = __floats2half2_rn(v.z, v.w);
    } else if (bid < 8192) {
        __shared__ float tile[32][33];
        const int widx = bid - 4096;
        const int z = widx >> 10;
        const int nb = (widx & 31) * 32;
        const int kb = ((widx >> 5) & 31) * 32;
        const float* W = (z == 0) ? wq : (z == 1) ? wk : (z == 2) ? wv : wo;
        __half* Wt = g_Wth + (size_t)z * DMODEL * DMODEL;
        const int tx = tid & 31;
        const int ty = tid >> 5;          // 0..7
#pragma unroll
        for (int j = 0; j < 4; j++) {
            const int r = ty + j * 8;     // k within tile
            tile[r][tx] = W[(size_t)(kb + r) * DMODEL + nb + tx];
        }
        __syncthreads();
#pragma unroll
        for (int j = 0; j < 4; j++) {
            const int r = ty + j * 8;     // n within tile
            Wt[(size_t)(nb + r) * DMODEL + kb + tx] =
                __float2half_rn(tile[tx][r]);
        }
    } else {
        const int gid = (bid - 8192) * 256 + tid;
        if (gid < BATCH * SEQ) {
            g_mbias[gid] = (mask[gid] != 0) ? 0.0f : -1e30f;
        } else if (gid - BATCH * SEQ < BATCH * 32) {
            const int t = gid - BATCH * SEQ;
            const int* mp = mask + (t >> 5) * SEQ + (t & 31) * 64;
            int anypad = 0;
#pragma unroll 8
            for (int i = 0; i < 64; i++) anypad |= (mp[i] == 0);
            g_tflag[t] = anypad;
        }
    }
}

// ---------------------------------------------------------------------------
// fp16 tensor-core GEMM (m16n8k16 + ldmatrix), 4-stage cp.async pipeline,
// statically unrolled stage rotation, one barrier/iter, warp-skewed k-order.
// (R13 config — best measured.)
// C[M,N] = A[M,K] @ W^T (W stored [N][K]) + bias
// BM=128 BN=128 BK=32, 256 thr (8 warps 2m x 4n), warp tile 64x32, 2 CTA/SM.
// MODE 0: fused QKV (z=blockIdx.z), head-split fp16 out
//         (z==0 pre-scaled by 0.125*log2e for base-2 softmax).
// MODE 1: Wo, fp32 row-major out.
// ---------------------------------------------------------------------------
#define APH 40
#define STGH 10240
#define GEMM_SMEM (4 * STGH * 2)   // 81920 B

template <int MODE>
__global__ __launch_bounds__(256, 2) void gemm_h(
    const float* __restrict__ b0p, const float* __restrict__ b1p,
    const float* __restrict__ b2p, float* __restrict__ outp)
{
    extern __shared__ __half sh[];

    const int z = (MODE == 0) ? blockIdx.z : 3;
    const __half* __restrict__ A = (MODE == 0) ? g_Xh : g_Ch;
    const __half* __restrict__ W = g_Wth + (size_t)z * DMODEL * DMODEL;
    const float* bias = (MODE == 0)
        ? ((z == 0) ? b0p : (z == 1) ? b1p : b2p) : b0p;
    __half* dstQ = (z == 0) ? g_Qh : (z == 1) ? g_Kh : g_Vh;

    const int tid = threadIdx.x;
    const int lane = tid & 31;
    const int warp = tid >> 5;
    const int g = lane >> 2;
    const int tg = lane & 3;
    const int m0 = blockIdx.y * 128;
    const int n0 = blockIdx.x * 128;
    const int wm = (warp >> 2) * 64;
    const int wn = (warp & 3) * 32;
    const int wskew = warp & 1;         // k-step order skew

    float acc[4][4][4];
#pragma unroll
    for (int mi = 0; mi < 4; mi++)
#pragma unroll
        for (int ni = 0; ni < 4; ni++)
#pragma unroll
            for (int q = 0; q < 4; q++) acc[mi][ni][q] = 0.0f;

    const int fr = tid >> 2;            // 0..63
    const int fk = (tid & 3) * 8;       // 0,8,16,24
    const __half* aSrc0 = A + (size_t)(m0 + fr) * DMODEL + fk;
    const __half* aSrc1 = aSrc0 + (size_t)64 * DMODEL;
    const __half* bSrc0 = W + (size_t)(n0 + fr) * DMODEL + fk;
    const __half* bSrc1 = bSrc0 + (size_t)64 * DMODEL;
    const int da0 = fr * APH + fk;
    const int da1 = (fr + 64) * APH + fk;
    const int db0 = 5120 + fr * APH + fk;
    const int db1 = 5120 + (fr + 64) * APH + fk;

    auto fill = [&](int t, int st) {
        __half* s = sh + st * STGH;
        const int k0 = t * 32;
        cpa16(s + da0, aSrc0 + k0);
        cpa16(s + da1, aSrc1 + k0);
        cpa16(s + db0, bSrc0 + k0);
        cpa16(s + db1, bSrc1 + k0);
    };

    const int lrow = lane & 15;
    const int lcol = (lane >> 4) * 8;

    auto compute = [&](int st) {
        const __half* As = sh + st * STGH;
        const __half* Bs = As + 5120;
#pragma unroll
        for (int ks = 0; ks < 2; ks++) {
            const int kb = (ks ^ wskew) * 16;   // warp-skewed order
            unsigned a[4][4], b[4][2];
#pragma unroll
            for (int mi = 0; mi < 4; mi++)
                ldsm4(a[mi],
                      smem_u32(As + (wm + mi * 16 + lrow) * APH + kb + lcol));
            {
                unsigned t0[4], t1[4];
                ldsm4(t0, smem_u32(Bs + (wn + lrow) * APH + kb + lcol));
                ldsm4(t1, smem_u32(Bs + (wn + 16 + lrow) * APH + kb + lcol));
                b[0][0] = t0[0]; b[1][0] = t0[1]; b[0][1] = t0[2]; b[1][1] = t0[3];
                b[2][0] = t1[0]; b[3][0] = t1[1]; b[2][1] = t1[2]; b[3][1] = t1[3];
            }
#pragma unroll
            for (int mi = 0; mi < 4; mi++)
#pragma unroll
                for (int ni = 0; ni < 4; ni++)
                    mma_f16(acc[mi][ni], a[mi], b[ni][0], b[ni][1]);
        }
    };

    auto step = [&](int t, int stc, int stf) {
        cp_wait<2>();
        __syncthreads();
        if (t + 3 < 32) fill(t + 3, stf);
        cp_commit();
        compute(stc);
    };

    fill(0, 0); cp_commit();
    fill(1, 1); cp_commit();
    fill(2, 2); cp_commit();

#pragma unroll 1
    for (int tb = 0; tb < 32; tb += 4) {
        step(tb + 0, 0, 3);
        step(tb + 1, 1, 0);
        step(tb + 2, 2, 1);
        step(tb + 3, 3, 2);
    }

    // epilogue (Q pre-scaled by 0.125*log2e -> base-2 softmax downstream)
    const float qsc = (MODE == 0 && z == 0) ? 0.18033688011112042f : 1.0f;
#pragma unroll
    for (int mi = 0; mi < 4; mi++) {
#pragma unroll
        for (int ni = 0; ni < 4; ni++) {
            const int row0 = m0 + wm + mi * 16 + g;
            const int row1 = row0 + 8;
            const int col = n0 + wn + ni * 8 + 2 * tg;
            const float bb0 = bias[col];
            const float bb1 = bias[col + 1];
            if (MODE == 1) {
                float2 v0 = make_float2(acc[mi][ni][0] + bb0,
                                        acc[mi][ni][1] + bb1);
                float2 v1 = make_float2(acc[mi][ni][2] + bb0,
                                        acc[mi][ni][3] + bb1);
                *reinterpret_cast<float2*>(&outp[(size_t)row0 * DMODEL + col]) = v0;
                *reinterpret_cast<float2*>(&outp[(size_t)row1 * DMODEL + col]) = v1;
            } else {
                __half2 h0 = __floats2half2_rn((acc[mi][ni][0] + bb0) * qsc,
                                               (acc[mi][ni][1] + bb1) * qsc);
                __half2 h1 = __floats2half2_rn((acc[mi][ni][2] + bb0) * qsc,
                                               (acc[mi][ni][3] + bb1) * qsc);
                const int h = col >> 6;
                const int d = col & (HD - 1);
                {
                    const int b = row0 >> 11, s = row0 & (SEQ - 1);
                    *reinterpret_cast<__half2*>(
                        &dstQ[((size_t)(b * NH + h) * SEQ + s) * HD + d]) = h0;
                }
                {
                    const int b = row1 >> 11, s = row1 & (SEQ - 1);
                    *reinterpret_cast<__half2*>(
                        &dstQ[((size_t)(b * NH + h) * SEQ + s) * HD + d]) = h1;
                }
            }
        }
    }
}

// ---------------------------------------------------------------------------
// fp16 flash attention (m16n8k16) — R13 pipeline, base-2 softmax (Q carries
// log2e), deferred l-reduction (per-thread partials, one shuffle-reduce in
// the epilogue), and rescale-skip when no row in the warp got a new max.
// 128 threads (4 warps), 64 q/block, 64-key tiles, 3-stage cp.async,
// wrapped stage pointers, ONE __syncthreads per tile. 3 CTAs/SM.
// grid = (SEQ/64, BATCH*NH)
// ---------------------------------------------------------------------------
#define QPH 72
#define KVSH (2 * 64 * QPH)                        // halves per KV stage
#define FA_SMEM ((64 * QPH + 3 * KVSH) * 2)        // Q + 3 stages -> 64512 B

__global__ __launch_bounds__(128) void flash_h()
{
    extern __shared__ __half fsm[];
    __half* Qs = fsm;

    const int tid = threadIdx.x;
    const int lane = tid & 31;
    const int warp = tid >> 5;
    const int g = lane >> 2;
    const int tg = lane & 3;
    const int wm = warp * 16;
    const int lrow = lane & 15;
    const int lcol = (lane >> 4) * 8;

    const int bh = blockIdx.y;
    const int b = bh >> 4;
    const int h = bh & 15;
    const int qt = gridDim.x - 1 - blockIdx.x;   // heavy-first
    const int q0 = qt * 64;
    const size_t base = (size_t)bh * SEQ * HD;

    auto fillkv = [&](int kt, __half* Kd) {
        __half* Vd = Kd + 64 * QPH;
        const int k0 = kt * 64;
#pragma unroll
        for (int u = 0; u < 8; u++) {
            const int c = tid + 128 * u;          // 0..1023
            if (u < 4) {
                const int r = c >> 3, cc = (c & 7) * 8;
                cpa16(Kd + r * QPH + cc, g_Kh + base + (size_t)(k0 + r) * HD + cc);
            } else {
                const int c2 = c - 512;
                const int r = c2 >> 3, cc = (c2 & 7) * 8;
                cpa16(Vd + r * QPH + cc, g_Vh + base + (size_t)(k0 + r) * HD + cc);
            }
        }
    };

    __half* const kvbase = fsm + 64 * QPH;
    __half* const kvend  = kvbase + 3 * KVSH;

#pragma unroll
    for (int u = 0; u < 4; u++) {
        const int c = tid + 128 * u;              // 0..511
        const int r = c >> 3, cc = (c & 7) * 8;
        cpa16(Qs + r * QPH + cc, g_Qh + base + (size_t)(q0 + r) * HD + cc);
    }
    fillkv(0, kvbase);
    cp_commit();
    if (qt >= 1) fillkv(1, kvbase + KVSH);
    cp_commit();

    cp_wait<1>();
    __syncthreads();

    unsigned qf[4][4];
#pragma unroll
    for (int j = 0; j < 4; j++)
        ldsm4(qf[j], smem_u32(Qs + (wm + lrow) * QPH + j * 16 + lcol));

    float o[8][4];
#pragma unroll
    for (int nt = 0; nt < 8; nt++)
#pragma unroll
        for (int q = 0; q < 4; q++) o[nt][q] = 0.0f;
    float m0r = -1e30f, m1r = -1e30f;
    float l0 = 0.0f, l1 = 0.0f;        // PER-THREAD partials (reduced at end)

    const int qr0 = q0 + wm + g;
    const int qr1 = qr0 + 8;
    const float* mb = g_mbias + b * SEQ;
    const int* tfl = g_tflag + (b << 5);

    __half* KsP = kvbase;
    __half* KfP = kvbase + 2 * KVSH;

#pragma unroll 1
    for (int kt = 0; kt <= qt; kt++) {
        const int k0 = kt * 64;
        cp_wait<1>();
        __syncthreads();
        if (kt + 2 <= qt) fillkv(kt + 2, KfP);
        cp_commit();

        const int need_pad = tfl[kt];
        const __half* Ks = KsP;
        const __half* Vs = KsP + 64 * QPH;
        const bool diag = (kt == qt);

        // --- S = Q' K^T (base-2 domain: Q' carries log2e/8) ---
        float S[8][4];
#pragma unroll
        for (int nt = 0; nt < 8; nt++)
#pragma unroll
            for (int q = 0; q < 4; q++) S[nt][q] = 0.0f;
#pragma unroll
        for (int j = 0; j < 4; j++) {
            const int kb = j * 16;
            unsigned bf[8][2];
#pragma unroll
            for (int p = 0; p < 4; p++) {
                unsigned tt[4];
                ldsm4(tt, smem_u32(Ks + (p * 16 + lrow) * QPH + kb + lcol));
                bf[2 * p][0] = tt[0]; bf[2 * p + 1][0] = tt[1];
                bf[2 * p][1] = tt[2]; bf[2 * p + 1][1] = tt[3];
            }
#pragma unroll
            for (int nt = 0; nt < 8; nt++)
                mma_f16(S[nt], qf[j], bf[nt][0], bf[nt][1]);
        }

        if (diag) {
#pragma unroll
            for (int nt = 0; nt < 8; nt++) {
                const int kk0 = k0 + nt * 8 + 2 * tg;
#pragma unroll
                for (int j = 0; j < 2; j++) {
                    const int kk = kk0 + j;
                    if (kk > qr0) S[nt][j] = -1e30f;
                    if (kk > qr1) S[nt][2 + j] = -1e30f;
                }
            }
        }
        if (need_pad) {
#pragma unroll
            for (int nt = 0; nt < 8; nt++) {
                const float2 bb = *reinterpret_cast<const float2*>(
                    mb + k0 + nt * 8 + 2 * tg);
                S[nt][0] += bb.x; S[nt][1] += bb.y;
                S[nt][2] += bb.x; S[nt][3] += bb.y;
            }
        }

        // --- online softmax (base 2) ---
        float mt0 = -1e30f, mt1 = -1e30f;
#pragma unroll
        for (int nt = 0; nt < 8; nt++) {
            mt0 = fmaxf(mt0, fmaxf(S[nt][0], S[nt][1]));
            mt1 = fmaxf(mt1, fmaxf(S[nt][2], S[nt][3]));
        }
        mt0 = fmaxf(mt0, __shfl_xor_sync(0xffffffffu, mt0, 1));
        mt0 = fmaxf(mt0, __shfl_xor_sync(0xffffffffu, mt0, 2));
        mt1 = fmaxf(mt1, __shfl_xor_sync(0xffffffffu, mt1, 1));
        mt1 = fmaxf(mt1, __shfl_xor_sync(0xffffffffu, mt1, 2));
        const float mn0 = fmaxf(m0r, mt0);
        const float mn1 = fmaxf(m1r, mt1);
        const float a0 = ex2f(m0r - mn0);
        const float a1 = ex2f(m1r - mn1);
        const bool newmax = (mn0 > m0r) | (mn1 > m1r);

        // --- P (registers only) ---
        unsigned pa[4][4];
        float s0 = 0.0f, s1 = 0.0f;
#pragma unroll
        for (int nt = 0; nt < 8; nt++) {
            const float p00 = ex2f(S[nt][0] - mn0);
            const float p01 = ex2f(S[nt][1] - mn0);
            const float p10 = ex2f(S[nt][2] - mn1);
            const float p11 = ex2f(S[nt][3] - mn1);
            s0 += p00 + p01;
            s1 += p10 + p11;
            const int j = nt >> 1;
            const int hh = (nt & 1) * 2;
            pa[j][hh]     = h2u(__floats2half2_rn(p00, p01));
            pa[j][hh + 1] = h2u(__floats2half2_rn(p10, p11));
        }
        // per-thread l partials (row reduce deferred to epilogue)
        l0 = l0 * a0 + s0;
        l1 = l1 * a1 + s1;
        m0r = mn0;
        m1r = mn1;
        // rescale o only if some row in the warp got a new max (else a==1)
        if (__any_sync(0xffffffffu, newmax)) {
#pragma unroll
            for (int nt = 0; nt < 8; nt++) {
                o[nt][0] *= a0; o[nt][1] *= a0;
                o[nt][2] *= a1; o[nt][3] *= a1;
            }
        }

        // --- O += P V (V fragments via ldmatrix.trans) ---
#pragma unroll
        for (int j = 0; j < 4; j++) {
            const int kb = j * 16;
            unsigned bv[8][2];
#pragma unroll
            for (int p = 0; p < 4; p++) {
                unsigned tt[4];
                ldsm4t(tt, smem_u32(
                    Vs + (kb + (lane >> 4) * 8 + (lane & 7)) * QPH
                       + 8 * (2 * p + ((lane >> 3) & 1))));
                bv[2 * p][0] = tt[0]; bv[2 * p + 1][0] = tt[1];
                bv[2 * p][1] = tt[2]; bv[2 * p + 1][1] = tt[3];
            }
#pragma unroll
            for (int nt = 0; nt < 8; nt++)
                mma_f16(o[nt], pa[j], bv[nt][0], bv[nt][1]);
        }

        KsP += KVSH; if (KsP == kvend) KsP = kvbase;
        KfP += KVSH; if (KfP == kvend) KfP = kvbase;
    }

    // --- epilogue: reduce l across the 4 lanes of each row group, store ---
    l0 += __shfl_xor_sync(0xffffffffu, l0, 1);
    l0 += __shfl_xor_sync(0xffffffffu, l0, 2);
    l1 += __shfl_xor_sync(0xffffffffu, l1, 1);
    l1 += __shfl_xor_sync(0xffffffffu, l1, 2);
    const float i0 = 1.0f / l0;
    const float i1 = 1.0f / l1;
#pragma unroll
    for (int nt = 0; nt < 8; nt++) {
        const int d = nt * 8 + 2 * tg;
        __half* p0 = &g_Ch[((size_t)(b * SEQ + qr0)) * DMODEL + h * HD + d];
        __half* p1 = &g_Ch[((size_t)(b * SEQ + qr1)) * DMODEL + h * HD + d];
        *reinterpret_cast<__half2*>(p0) =
            __floats2half2_rn(o[nt][0] * i0, o[nt][1] * i0);
        *reinterpret_cast<__half2*>(p1) =
            __floats2half2_rn(o[nt][2] * i1, o[nt][3] * i1);
    }
}

// ---------------------------------------------------------------------------
extern "C" void kernel_launch(void* const* d_in, const int* in_sizes, int n_in,
                              void* d_out, int out_size)
{
    const float* x     = (const float*)d_in[0];
    const int*   amask = (const int*)  d_in[1];
    const float* Wq    = (const float*)d_in[2];
    const float* bq    = (const float*)d_in[3];
    const float* Wk    = (const float*)d_in[4];
    const float* bk    = (const float*)d_in[5];
    const float* Wv    = (const float*)d_in[6];
    const float* bv    = (const float*)d_in[7];
    const float* Wo    = (const float*)d_in[8];
    const float* bo    = (const float*)d_in[9];
    float* out = (float*)d_out;

    // 1. merged prep: x -> fp16, weights -> transposed fp16, mask -> bias
    prep_all<<<8209, 256>>>((const float4*)x, Wq, Wk, Wv, Wo, amask);

    cudaFuncSetAttribute(gemm_h<0>,
                         cudaFuncAttributeMaxDynamicSharedMemorySize, GEMM_SMEM);
    cudaFuncSetAttribute(gemm_h<1>,
                         cudaFuncAttributeMaxDynamicSharedMemorySize, GEMM_SMEM);

    // 2. fused QKV projection
    gemm_h<0><<<dim3(DMODEL / 128, MROWS / 128, 3), 256, GEMM_SMEM>>>(
        bq, bk, bv, nullptr);

    // 3. flash attention
    cudaFuncSetAttribute(flash_h,
                         cudaFuncAttributeMaxDynamicSharedMemorySize, FA_SMEM);
    flash_h<<<dim3(SEQ / 64, BATCH * NH), 128, FA_SMEM>>>();

    // 4. output projection
    gemm_h<1><<<dim3(DMODEL / 128, MROWS / 128, 1), 256, GEMM_SMEM>>>(
        bo, nullptr, nullptr, out);
}

// round 16
// speedup vs baseline: 1.0074x; 1.0046x over previous
#include <cuda_runtime.h>
#include <cuda_fp16.h>
#include <cstdint>

#define BATCH 2
#define SEQ 2048
#define DMODEL 1024
#define NH 16
#define HD 64
#define MROWS (BATCH * SEQ)   // 4096

// Scratch (allocation-free rule: __device__ globals)
__device__ __half g_Xh[MROWS * DMODEL];          // x in fp16
__device__ __half g_Qh[MROWS * DMODEL];          // (B,H,S,hd), scaled log2e/8
__device__ __half g_Kh[MROWS * DMODEL];
__device__ __half g_Vh[MROWS * DMODEL];
__device__ __half g_Ch[MROWS * DMODEL];          // ctx (B,S,D) fp16
__device__ __half g_Wth[4 * DMODEL * DMODEL];    // weights [N][K] fp16
__device__ float  g_mbias[BATCH * SEQ];          // 0 or -1e30 per key
__device__ int    g_tflag[BATCH * 32];           // per 64-key tile: has pad?

// ---------------------------------------------------------------------------
// helpers
// ---------------------------------------------------------------------------
__device__ __forceinline__ void mma_f16(float* c, const unsigned* a,
                                        unsigned b0, unsigned b1) {
    asm volatile(
        "mma.sync.aligned.m16n8k16.row.col.f32.f16.f16.f32 "
        "{%0,%1,%2,%3}, {%4,%5,%6,%7}, {%8,%9}, {%0,%1,%2,%3};"
        : "+f"(c[0]), "+f"(c[1]), "+f"(c[2]), "+f"(c[3])
        : "r"(a[0]), "r"(a[1]), "r"(a[2]), "r"(a[3]), "r"(b0), "r"(b1));
}

__device__ __forceinline__ uint32_t smem_u32(const void* p) {
    return (uint32_t)__cvta_generic_to_shared(p);
}
__device__ __forceinline__ void ldsm4(unsigned* r, uint32_t a) {
    asm volatile("ldmatrix.sync.aligned.m8n8.x4.shared.b16 {%0,%1,%2,%3}, [%4];"
                 : "=r"(r[0]), "=r"(r[1]), "=r"(r[2]), "=r"(r[3]) : "r"(a));
}
__device__ __forceinline__ void ldsm4t(unsigned* r, uint32_t a) {
    asm volatile("ldmatrix.sync.aligned.m8n8.x4.trans.shared.b16 {%0,%1,%2,%3}, [%4];"
                 : "=r"(r[0]), "=r"(r[1]), "=r"(r[2]), "=r"(r[3]) : "r"(a));
}
__device__ __forceinline__ unsigned h2u(__half2 h) {
    return *reinterpret_cast<unsigned*>(&h);
}
__device__ __forceinline__ float ex2f(float x) {   // raw 2^x, single MUFU op
    float r;
    asm("ex2.approx.f32 %0, %1;" : "=f"(r) : "f"(x));
    return r;
}

__device__ __forceinline__ void cpa16(void* s, const void* g) {
    unsigned a = (unsigned)__cvta_generic_to_shared(s);
    asm volatile("cp.async.cg.shared.global [%0], [%1], 16;" :: "r"(a), "l"(g));
}
__device__ __forceinline__ void cp_commit() {
    asm volatile("cp.async.commit_group;");
}
template <int N>
__device__ __forceinline__ void cp_wait() {
    asm volatile("cp.async.wait_group %0;" :: "n"(N));
}

// ---------------------------------------------------------------------------
// merged prep kernel (one launch):
//   bid [0, 4096)      : x -> fp16 (1M float4)
//   bid [4096, 8192)   : W[K][N] fp32 -> g_Wth[N][K] fp16 (transposed)
//   bid [8192, 8209)   : mask -> bias + per-tile pad flags
// ---------------------------------------------------------------------------
__global__ __launch_bounds__(256) void prep_all(
    const float4* __restrict__ x,
    const float* __restrict__ wq, const float* __restrict__ wk,
    const float* __restrict__ wv, const float* __restrict__ wo,
    const int* __restrict__ mask)
{
    const int bid = blockIdx.x;
    const int tid = threadIdx.x;

    if (bid < 4096) {
        const int i = bid * 256 + tid;
        float4 v = x[i];
        __half2* dst = reinterpret_cast<__half2*>(g_Xh);
        dst[2 * i]     = __floats2half2_rn(v.x, v.y);
        dst[2 * i + 1] = __floats2half2_rn(v.z, v.w);
    } else if (bid < 8192) {
        __shared__ float tile[32][33];
        const int widx = bid - 4096;
        const int z = widx >> 10;
        const int nb = (widx & 31) * 32;
        const int kb = ((widx >> 5) & 31) * 32;
        const float* W = (z == 0) ? wq : (z == 1) ? wk : (z == 2) ? wv : wo;
        __half* Wt = g_Wth + (size_t)z * DMODEL * DMODEL;
        const int tx = tid & 31;
        const int ty = tid >> 5;          // 0..7
#pragma unroll
        for (int j = 0; j < 4; j++) {
            const int r = ty + j * 8;     // k within tile
            tile[r][tx] = W[(size_t)(kb + r) * DMODEL + nb + tx];
        }
        __syncthreads();
#pragma unroll
        for (int j = 0; j < 4; j++) {
            const int r = ty + j * 8;     // n within tile
            Wt[(size_t)(nb + r) * DMODEL + kb + tx] =
                __float2half_rn(tile[tx][r]);
        }
    } else {
        const int gid = (bid - 8192) * 256 + tid;
        if (gid < BATCH * SEQ) {
            g_mbias[gid] = (mask[gid] != 0) ? 0.0f : -1e30f;
        } else if (gid - BATCH * SEQ < BATCH * 32) {
            const int t = gid - BATCH * SEQ;
            const int* mp = mask + (t >> 5) * SEQ + (t & 31) * 64;
            int anypad = 0;
#pragma unroll 8
            for (int i = 0; i < 64; i++) anypad |= (mp[i] == 0);
            g_tflag[t] = anypad;
        }
    }
}

// ---------------------------------------------------------------------------
// fp16 tensor-core GEMM (m16n8k16 + ldmatrix), 4-stage cp.async pipeline,
// statically unrolled stage rotation, one barrier/iter, warp-skewed k-order.
// (R13/R15 config — best measured.)
// C[M,N] = A[M,K] @ W^T (W stored [N][K]) + bias
// BM=128 BN=128 BK=32, 256 thr (8 warps 2m x 4n), warp tile 64x32, 2 CTA/SM.
// MODE 0: fused QKV (z=blockIdx.z), head-split fp16 out
//         (z==0 pre-scaled by 0.125*log2e for base-2 softmax).
// MODE 1: Wo, fp32 row-major out.
// ---------------------------------------------------------------------------
#define APH 40
#define STGH 10240
#define GEMM_SMEM (4 * STGH * 2)   // 81920 B

template <int MODE>
__global__ __launch_bounds__(256, 2) void gemm_h(
    const float* __restrict__ b0p, const float* __restrict__ b1p,
    const float* __restrict__ b2p, float* __restrict__ outp)
{
    extern __shared__ __half sh[];

    const int z = (MODE == 0) ? blockIdx.z : 3;
    const __half* __restrict__ A = (MODE == 0) ? g_Xh : g_Ch;
    const __half* __restrict__ W = g_Wth + (size_t)z * DMODEL * DMODEL;
    const float* bias = (MODE == 0)
        ? ((z == 0) ? b0p : (z == 1) ? b1p : b2p) : b0p;
    __half* dstQ = (z == 0) ? g_Qh : (z == 1) ? g_Kh : g_Vh;

    const int tid = threadIdx.x;
    const int lane = tid & 31;
    const int warp = tid >> 5;
    const int g = lane >> 2;
    const int tg = lane & 3;
    const int m0 = blockIdx.y * 128;
    const int n0 = blockIdx.x * 128;
    const int wm = (warp >> 2) * 64;
    const int wn = (warp & 3) * 32;
    const int wskew = warp & 1;         // k-step order skew

    float acc[4][4][4];
#pragma unroll
    for (int mi = 0; mi < 4; mi++)
#pragma unroll
        for (int ni = 0; ni < 4; ni++)
#pragma unroll
            for (int q = 0; q < 4; q++) acc[mi][ni][q] = 0.0f;

    const int fr = tid >> 2;            // 0..63
    const int fk = (tid & 3) * 8;       // 0,8,16,24
    const __half* aSrc0 = A + (size_t)(m0 + fr) * DMODEL + fk;
    const __half* aSrc1 = aSrc0 + (size_t)64 * DMODEL;
    const __half* bSrc0 = W + (size_t)(n0 + fr) * DMODEL + fk;
    const __half* bSrc1 = bSrc0 + (size_t)64 * DMODEL;
    const int da0 = fr * APH + fk;
    const int da1 = (fr + 64) * APH + fk;
    const int db0 = 5120 + fr * APH + fk;
    const int db1 = 5120 + (fr + 64) * APH + fk;

    auto fill = [&](int t, int st) {
        __half* s = sh + st * STGH;
        const int k0 = t * 32;
        cpa16(s + da0, aSrc0 + k0);
        cpa16(s + da1, aSrc1 + k0);
        cpa16(s + db0, bSrc0 + k0);
        cpa16(s + db1, bSrc1 + k0);
    };

    const int lrow = lane & 15;
    const int lcol = (lane >> 4) * 8;

    auto compute = [&](int st) {
        const __half* As = sh + st * STGH;
        const __half* Bs = As + 5120;
#pragma unroll
        for (int ks = 0; ks < 2; ks++) {
            const int kb = (ks ^ wskew) * 16;   // warp-skewed order
            unsigned a[4][4], b[4][2];
#pragma unroll
            for (int mi = 0; mi < 4; mi++)
                ldsm4(a[mi],
                      smem_u32(As + (wm + mi * 16 + lrow) * APH + kb + lcol));
            {
                unsigned t0[4], t1[4];
                ldsm4(t0, smem_u32(Bs + (wn + lrow) * APH + kb + lcol));
                ldsm4(t1, smem_u32(Bs + (wn + 16 + lrow) * APH + kb + lcol));
                b[0][0] = t0[0]; b[1][0] = t0[1]; b[0][1] = t0[2]; b[1][1] = t0[3];
                b[2][0] = t1[0]; b[3][0] = t1[1]; b[2][1] = t1[2]; b[3][1] = t1[3];
            }
#pragma unroll
            for (int mi = 0; mi < 4; mi++)
#pragma unroll
                for (int ni = 0; ni < 4; ni++)
                    mma_f16(acc[mi][ni], a[mi], b[ni][0], b[ni][1]);
        }
    };

    auto step = [&](int t, int stc, int stf) {
        cp_wait<2>();
        __syncthreads();
        if (t + 3 < 32) fill(t + 3, stf);
        cp_commit();
        compute(stc);
    };

    fill(0, 0); cp_commit();
    fill(1, 1); cp_commit();
    fill(2, 2); cp_commit();

#pragma unroll 1
    for (int tb = 0; tb < 32; tb += 4) {
        step(tb + 0, 0, 3);
        step(tb + 1, 1, 0);
        step(tb + 2, 2, 1);
        step(tb + 3, 3, 2);
    }

    // epilogue (Q pre-scaled by 0.125*log2e -> base-2 softmax downstream)
    const float qsc = (MODE == 0 && z == 0) ? 0.18033688011112042f : 1.0f;
#pragma unroll
    for (int mi = 0; mi < 4; mi++) {
#pragma unroll
        for (int ni = 0; ni < 4; ni++) {
            const int row0 = m0 + wm + mi * 16 + g;
            const int row1 = row0 + 8;
            const int col = n0 + wn + ni * 8 + 2 * tg;
            const float bb0 = bias[col];
            const float bb1 = bias[col + 1];
            if (MODE == 1) {
                float2 v0 = make_float2(acc[mi][ni][0] + bb0,
                                        acc[mi][ni][1] + bb1);
                float2 v1 = make_float2(acc[mi][ni][2] + bb0,
                                        acc[mi][ni][3] + bb1);
                *reinterpret_cast<float2*>(&outp[(size_t)row0 * DMODEL + col]) = v0;
                *reinterpret_cast<float2*>(&outp[(size_t)row1 * DMODEL + col]) = v1;
            } else {
                __half2 h0 = __floats2half2_rn((acc[mi][ni][0] + bb0) * qsc,
                                               (acc[mi][ni][1] + bb1) * qsc);
                __half2 h1 = __floats2half2_rn((acc[mi][ni][2] + bb0) * qsc,
                                               (acc[mi][ni][3] + bb1) * qsc);
                const int h = col >> 6;
                const int d = col & (HD - 1);
                {
                    const int b = row0 >> 11, s = row0 & (SEQ - 1);
                    *reinterpret_cast<__half2*>(
                        &dstQ[((size_t)(b * NH + h) * SEQ + s) * HD + d]) = h0;
                }
                {
                    const int b = row1 >> 11, s = row1 & (SEQ - 1);
                    *reinterpret_cast<__half2*>(
                        &dstQ[((size_t)(b * NH + h) * SEQ + s) * HD + d]) = h1;
                }
            }
        }
    }
}

// ---------------------------------------------------------------------------
// fp16 flash attention (m16n8k16) — R15 math, with Q-buffer/stage-2 smem
// OVERLAY: total smem drops 64.5 KB -> 54 KB, lifting occupancy 3 -> 4
// CTAs/SM (12 -> 16 warps). Safe because stage-ovl's first fill is ordered
// after all warps' Q-fragment loads by the kt=0 barrier.
// Layout: [ovl stage (Q lives in its first half until consumed)]
//         [stage A][stage B].  kt=0->A, kt=1->B, kt=2->ovl, ring A->B->ovl.
// 128 threads (4 warps), 64 q/block, 64-key tiles, 3-stage cp.async,
// wrapped stage pointers, ONE __syncthreads per tile, base-2 softmax,
// deferred l-reduction, rescale-skip. Heavy-first block order.
// grid = (SEQ/64, BATCH*NH)
// ---------------------------------------------------------------------------
#define QPH 72
#define KVSH (2 * 64 * QPH)                 // halves per KV stage (18432 B)
#define FA_SMEM (3 * KVSH * 2)              // 55296 B -> 4 CTAs/SM

__global__ __launch_bounds__(128, 4) void flash_h()
{
    extern __shared__ __half fsm[];
    __half* Qs = fsm;                       // overlaid with stage-ovl

    const int tid = threadIdx.x;
    const int lane = tid & 31;
    const int warp = tid >> 5;
    const int g = lane >> 2;
    const int tg = lane & 3;
    const int wm = warp * 16;
    const int lrow = lane & 15;
    const int lcol = (lane >> 4) * 8;

    const int bh = blockIdx.y;
    const int b = bh >> 4;
    const int h = bh & 15;
    const int qt = gridDim.x - 1 - blockIdx.x;   // heavy-first
    const int q0 = qt * 64;
    const size_t base = (size_t)bh * SEQ * HD;

    auto fillkv = [&](int kt, __half* Kd) {
        __half* Vd = Kd + 64 * QPH;
        const int k0 = kt * 64;
#pragma unroll
        for (int u = 0; u < 8; u++) {
            const int c = tid + 128 * u;          // 0..1023
            if (u < 4) {
                const int r = c >> 3, cc = (c & 7) * 8;
                cpa16(Kd + r * QPH + cc, g_Kh + base + (size_t)(k0 + r) * HD + cc);
            } else {
                const int c2 = c - 512;
                const int r = c2 >> 3, cc = (c2 & 7) * 8;
                cpa16(Vd + r * QPH + cc, g_Vh + base + (size_t)(k0 + r) * HD + cc);
            }
        }
    };

    __half* const stOvl = fsm;                  // stage for kt%3==2 (and Q)
    __half* const stA   = fsm + KVSH;           // stage for kt%3==0
    __half* const kvend = fsm + 3 * KVSH;

    // prologue: Q (into ovl region) + stage A in group 1; stage B in group 2
#pragma unroll
    for (int u = 0; u < 4; u++) {
        const int c = tid + 128 * u;              // 0..511
        const int r = c >> 3, cc = (c & 7) * 8;
        cpa16(Qs + r * QPH + cc, g_Qh + base + (size_t)(q0 + r) * HD + cc);
    }
    fillkv(0, stA);
    cp_commit();
    if (qt >= 1) fillkv(1, stA + KVSH);
    cp_commit();

    cp_wait<1>();            // group 1 (Q + KV0) complete
    __syncthreads();

    // Q fragments (4 k-steps over hd=64) — Q region is dead after this;
    // the kt=0 barrier below orders these loads before fill of stOvl.
    unsigned qf[4][4];
#pragma unroll
    for (int j = 0; j < 4; j++)
        ldsm4(qf[j], smem_u32(Qs + (wm + lrow) * QPH + j * 16 + lcol));

    float o[8][4];
#pragma unroll
    for (int nt = 0; nt < 8; nt++)
#pragma unroll
        for (int q = 0; q < 4; q++) o[nt][q] = 0.0f;
    float m0r = -1e30f, m1r = -1e30f;
    float l0 = 0.0f, l1 = 0.0f;        // per-thread partials

    const int qr0 = q0 + wm + g;
    const int qr1 = qr0 + 8;
    const float* mb = g_mbias + b * SEQ;
    const int* tfl = g_tflag + (b << 5);

    __half* KsP = stA;                 // compute stage for kt (ring A->B->ovl)
    __half* KfP = stOvl;               // fill stage for kt+2

#pragma unroll 1
    for (int kt = 0; kt <= qt; kt++) {
        const int k0 = kt * 64;
        cp_wait<1>();
        __syncthreads();       // also orders Q-frag loads before ovl fill
        if (kt + 2 <= qt) fillkv(kt + 2, KfP);
        cp_commit();

        const int need_pad = tfl[kt];
        const __half* Ks = KsP;
        const __half* Vs = KsP + 64 * QPH;
        const bool diag = (kt == qt);

        // --- S = Q' K^T (base-2 domain) ---
        float S[8][4];
#pragma unroll
        for (int nt = 0; nt < 8; nt++)
#pragma unroll
            for (int q = 0; q < 4; q++) S[nt][q] = 0.0f;
#pragma unroll
        for (int j = 0; j < 4; j++) {
            const int kb = j * 16;
            unsigned bf[8][2];
#pragma unroll
            for (int p = 0; p < 4; p++) {
                unsigned tt[4];
                ldsm4(tt, smem_u32(Ks + (p * 16 + lrow) * QPH + kb + lcol));
                bf[2 * p][0] = tt[0]; bf[2 * p + 1][0] = tt[1];
                bf[2 * p][1] = tt[2]; bf[2 * p + 1][1] = tt[3];
            }
#pragma unroll
            for (int nt = 0; nt < 8; nt++)
                mma_f16(S[nt], qf[j], bf[nt][0], bf[nt][1]);
        }

        if (diag) {
#pragma unroll
            for (int nt = 0; nt < 8; nt++) {
                const int kk0 = k0 + nt * 8 + 2 * tg;
#pragma unroll
                for (int j = 0; j < 2; j++) {
                    const int kk = kk0 + j;
                    if (kk > qr0) S[nt][j] = -1e30f;
                    if (kk > qr1) S[nt][2 + j] = -1e30f;
                }
            }
        }
        if (need_pad) {
#pragma unroll
            for (int nt = 0; nt < 8; nt++) {
                const float2 bb = *reinterpret_cast<const float2*>(
                    mb + k0 + nt * 8 + 2 * tg);
                S[nt][0] += bb.x; S[nt][1] += bb.y;
                S[nt][2] += bb.x; S[nt][3] += bb.y;
            }
        }

        // --- online softmax (base 2) ---
        float mt0 = -1e30f, mt1 = -1e30f;
#pragma unroll
        for (int nt = 0; nt < 8; nt++) {
            mt0 = fmaxf(mt0, fmaxf(S[nt][0], S[nt][1]));
            mt1 = fmaxf(mt1, fmaxf(S[nt][2], S[nt][3]));
        }
        mt0 = fmaxf(mt0, __shfl_xor_sync(0xffffffffu, mt0, 1));
        mt0 = fmaxf(mt0, __shfl_xor_sync(0xffffffffu, mt0, 2));
        mt1 = fmaxf(mt1, __shfl_xor_sync(0xffffffffu, mt1, 1));
        mt1 = fmaxf(mt1, __shfl_xor_sync(0xffffffffu, mt1, 2));
        const float mn0 = fmaxf(m0r, mt0);
        const float mn1 = fmaxf(m1r, mt1);
        const float a0 = ex2f(m0r - mn0);
        const float a1 = ex2f(m1r - mn1);
        const bool newmax = (mn0 > m0r) | (mn1 > m1r);

        // --- P (registers only) ---
        unsigned pa[4][4];
        float s0 = 0.0f, s1 = 0.0f;
#pragma unroll
        for (int nt = 0; nt < 8; nt++) {
            const float p00 = ex2f(S[nt][0] - mn0);
            const float p01 = ex2f(S[nt][1] - mn0);
            const float p10 = ex2f(S[nt][2] - mn1);
            const float p11 = ex2f(S[nt][3] - mn1);
            s0 += p00 + p01;
            s1 += p10 + p11;
            const int j = nt >> 1;
            const int hh = (nt & 1) * 2;
            pa[j][hh]     = h2u(__floats2half2_rn(p00, p01));
            pa[j][hh + 1] = h2u(__floats2half2_rn(p10, p11));
        }
        l0 = l0 * a0 + s0;
        l1 = l1 * a1 + s1;
        m0r = mn0;
        m1r = mn1;
        if (__any_sync(0xffffffffu, newmax)) {
#pragma unroll
            for (int nt = 0; nt < 8; nt++) {
                o[nt][0] *= a0; o[nt][1] *= a0;
                o[nt][2] *= a1; o[nt][3] *= a1;
            }
        }

        // --- O += P V (V fragments via ldmatrix.trans) ---
#pragma unroll
        for (int j = 0; j < 4; j++) {
            const int kb = j * 16;
            unsigned bv[8][2];
#pragma unroll
            for (int p = 0; p < 4; p++) {
                unsigned tt[4];
                ldsm4t(tt, smem_u32(
                    Vs + (kb + (lane >> 4) * 8 + (lane & 7)) * QPH
                       + 8 * (2 * p + ((lane >> 3) & 1))));
                bv[2 * p][0] = tt[0]; bv[2 * p + 1][0] = tt[1];
                bv[2 * p][1] = tt[2]; bv[2 * p + 1][1] = tt[3];
            }
#pragma unroll
            for (int nt = 0; nt < 8; nt++)
                mma_f16(o[nt], pa[j], bv[nt][0], bv[nt][1]);
        }

        KsP += KVSH; if (KsP == kvend) KsP = fsm;
        KfP += KVSH; if (KfP == kvend) KfP = fsm;
    }

    // --- epilogue: reduce l across the 4 lanes of each row group, store ---
    l0 += __shfl_xor_sync(0xffffffffu, l0, 1);
    l0 += __shfl_xor_sync(0xffffffffu, l0, 2);
    l1 += __shfl_xor_sync(0xffffffffu, l1, 1);
    l1 += __shfl_xor_sync(0xffffffffu, l1, 2);
    const float i0 = 1.0f / l0;
    const float i1 = 1.0f / l1;
#pragma unroll
    for (int nt = 0; nt < 8; nt++) {
        const int d = nt * 8 + 2 * tg;
        __half* p0 = &g_Ch[((size_t)(b * SEQ + qr0)) * DMODEL + h * HD + d];
        __half* p1 = &g_Ch[((size_t)(b * SEQ + qr1)) * DMODEL + h * HD + d];
        *reinterpret_cast<__half2*>(p0) =
            __floats2half2_rn(o[nt][0] * i0, o[nt][1] * i0);
        *reinterpret_cast<__half2*>(p1) =
            __floats2half2_rn(o[nt][2] * i1, o[nt][3] * i1);
    }
}

// ---------------------------------------------------------------------------
extern "C" void kernel_launch(void* const* d_in, const int* in_sizes, int n_in,
                              void* d_out, int out_size)
{
    const float* x     = (const float*)d_in[0];
    const int*   amask = (const int*)  d_in[1];
    const float* Wq    = (const float*)d_in[2];
    const float* bq    = (const float*)d_in[3];
    const float* Wk    = (const float*)d_in[4];
    const float* bk    = (const float*)d_in[5];
    const float* Wv    = (const float*)d_in[6];
    const float* bv    = (const float*)d_in[7];
    const float* Wo    = (const float*)d_in[8];
    const float* bo    = (const float*)d_in[9];
    float* out = (float*)d_out;

    // 1. merged prep: x -> fp16, weights -> transposed fp16, mask -> bias
    prep_all<<<8209, 256>>>((const float4*)x, Wq, Wk, Wv, Wo, amask);

    cudaFuncSetAttribute(gemm_h<0>,
                         cudaFuncAttributeMaxDynamicSharedMemorySize, GEMM_SMEM);
    cudaFuncSetAttribute(gemm_h<1>,
                         cudaFuncAttributeMaxDynamicSharedMemorySize, GEMM_SMEM);

    // 2. fused QKV projection
    gemm_h<0><<<dim3(DMODEL / 128, MROWS / 128, 3), 256, GEMM_SMEM>>>(
        bq, bk, bv, nullptr);

    // 3. flash attention (4 CTAs/SM via Q/stage overlay)
    cudaFuncSetAttribute(flash_h,
                         cudaFuncAttributeMaxDynamicSharedMemorySize, FA_SMEM);
    flash_h<<<dim3(SEQ / 64, BATCH * NH), 128, FA_SMEM>>>();

    // 4. output projection
    gemm_h<1><<<dim3(DMODEL / 128, MROWS / 128, 1), 256, GEMM_SMEM>>>(
        bo, nullptr, nullptr, out);
}